// round 1
// baseline (speedup 1.0000x reference)
#include <cuda_runtime.h>
#include <cuda_bf16.h>
#include <math.h>

// Problem constants
#define BATCH 16
#define SEQ   2048
#define EMB   512
#define HID   1024

// Scratch (device globals: allocation-free per harness rules)
__device__ float g_scores[(long)BATCH * SEQ * SEQ];   // 256 MB
__device__ float g_attn  [(long)BATCH * SEQ * EMB];   // 64 MB
__device__ float g_x     [(long)BATCH * SEQ * EMB];   // 64 MB
__device__ float g_h     [(long)BATCH * SEQ * HID];   // 128 MB
__device__ float g_ff    [(long)BATCH * SEQ * EMB];   // 64 MB

__device__ __forceinline__ float gelu_exact(float x) {
    return 0.5f * x * (1.0f + erff(x * 0.70710678118654752f));
}

// ---------------------------------------------------------------------------
// Batched SGEMM: C = alpha * A * op(B) (+ bias, + gelu)
//   A: [M,K] row-major.  TRANS_B ? B:[N,K] row-major : B:[K,N] row-major.
//   EPI: 0 = scale by alpha, 1 = +bias then GELU, 2 = +bias
// Tile: 128x128x16, 256 threads, 8x8 per thread. All dims divide tiles exactly.
// ---------------------------------------------------------------------------
#define GBM 128
#define GBN 128
#define GBK 16

template <bool TRANS_B, int EPI>
__global__ __launch_bounds__(256) void gemm_k(
    const float* __restrict__ A, const float* __restrict__ B,
    const float* __restrict__ bias, float* __restrict__ C,
    int M, int N, int K, long sA, long sB, long sC, float alpha)
{
    __shared__ float As[GBK][GBM];
    __shared__ float Bs[GBK][GBN];

    const int bz = blockIdx.z;
    A += (long)bz * sA;
    B += (long)bz * sB;
    C += (long)bz * sC;

    const int bm = blockIdx.y * GBM;
    const int bn = blockIdx.x * GBN;
    const int tid = threadIdx.x;
    const int trow = (tid >> 4) << 3;   // 0..120
    const int tcol = (tid & 15) << 3;   // 0..120

    float acc[8][8];
#pragma unroll
    for (int i = 0; i < 8; i++)
#pragma unroll
        for (int j = 0; j < 8; j++) acc[i][j] = 0.0f;

    for (int k0 = 0; k0 < K; k0 += GBK) {
        // Load A tile (K-contiguous rows) -> transposed into As[k][m]
#pragma unroll
        for (int i = 0; i < 2; i++) {
            int idx = tid + i * 256;          // 512 float4 total
            int r = idx >> 2;                 // 0..127
            int c = (idx & 3) * 4;            // 0,4,8,12
            float4 vv = *(const float4*)&A[(long)(bm + r) * K + k0 + c];
            As[c + 0][r] = vv.x; As[c + 1][r] = vv.y;
            As[c + 2][r] = vv.z; As[c + 3][r] = vv.w;
        }
        if (TRANS_B) {
#pragma unroll
            for (int i = 0; i < 2; i++) {
                int idx = tid + i * 256;
                int r = idx >> 2;
                int c = (idx & 3) * 4;
                float4 vv = *(const float4*)&B[(long)(bn + r) * K + k0 + c];
                Bs[c + 0][r] = vv.x; Bs[c + 1][r] = vv.y;
                Bs[c + 2][r] = vv.z; Bs[c + 3][r] = vv.w;
            }
        } else {
#pragma unroll
            for (int i = 0; i < 2; i++) {
                int idx = tid + i * 256;
                int r = idx >> 5;               // 0..15
                int c = (idx & 31) * 4;         // 0..124
                float4 vv = *(const float4*)&B[(long)(k0 + r) * N + bn + c];
                *(float4*)&Bs[r][c] = vv;
            }
        }
        __syncthreads();

#pragma unroll
        for (int kk = 0; kk < GBK; kk++) {
            float ra[8], rb[8];
#pragma unroll
            for (int i = 0; i < 8; i++) ra[i] = As[kk][trow + i];
#pragma unroll
            for (int j = 0; j < 8; j++) rb[j] = Bs[kk][tcol + j];
#pragma unroll
            for (int i = 0; i < 8; i++)
#pragma unroll
                for (int j = 0; j < 8; j++)
                    acc[i][j] = fmaf(ra[i], rb[j], acc[i][j]);
        }
        __syncthreads();
    }

    // Epilogue
#pragma unroll
    for (int i = 0; i < 8; i++) {
        long row = bm + trow + i;
#pragma unroll
        for (int j = 0; j < 8; j += 4) {
            int col = bn + tcol + j;
            float4 vv;
            vv.x = acc[i][j + 0]; vv.y = acc[i][j + 1];
            vv.z = acc[i][j + 2]; vv.w = acc[i][j + 3];
            if (EPI == 0) {
                vv.x *= alpha; vv.y *= alpha; vv.z *= alpha; vv.w *= alpha;
            } else {
                float4 bv = *(const float4*)&bias[col];
                vv.x += bv.x; vv.y += bv.y; vv.z += bv.z; vv.w += bv.w;
                if (EPI == 1) {
                    vv.x = gelu_exact(vv.x); vv.y = gelu_exact(vv.y);
                    vv.z = gelu_exact(vv.z); vv.w = gelu_exact(vv.w);
                }
            }
            *(float4*)&C[row * N + col] = vv;
        }
    }
}

// ---------------------------------------------------------------------------
// Row softmax over 2048 columns, in place. One block (256 thr) per row.
// ---------------------------------------------------------------------------
__global__ __launch_bounds__(256) void softmax_k(float* __restrict__ sc)
{
    float* p = sc + (long)blockIdx.x * SEQ;
    const int tid = threadIdx.x;
    float4 a = ((const float4*)p)[tid];
    float4 b = ((const float4*)p)[tid + 256];

    float mx = fmaxf(fmaxf(fmaxf(a.x, a.y), fmaxf(a.z, a.w)),
                     fmaxf(fmaxf(b.x, b.y), fmaxf(b.z, b.w)));
#pragma unroll
    for (int o = 16; o; o >>= 1) mx = fmaxf(mx, __shfl_xor_sync(0xffffffffu, mx, o));

    __shared__ float red[8];
    if ((tid & 31) == 0) red[tid >> 5] = mx;
    __syncthreads();
    mx = red[0];
#pragma unroll
    for (int i = 1; i < 8; i++) mx = fmaxf(mx, red[i]);
    __syncthreads();

    a.x = expf(a.x - mx); a.y = expf(a.y - mx); a.z = expf(a.z - mx); a.w = expf(a.w - mx);
    b.x = expf(b.x - mx); b.y = expf(b.y - mx); b.z = expf(b.z - mx); b.w = expf(b.w - mx);
    float s = a.x + a.y + a.z + a.w + b.x + b.y + b.z + b.w;
#pragma unroll
    for (int o = 16; o; o >>= 1) s += __shfl_xor_sync(0xffffffffu, s, o);
    if ((tid & 31) == 0) red[tid >> 5] = s;
    __syncthreads();
    s = red[0] + red[1] + red[2] + red[3] + red[4] + red[5] + red[6] + red[7];

    float inv = 1.0f / s;
    a.x *= inv; a.y *= inv; a.z *= inv; a.w *= inv;
    b.x *= inv; b.y *= inv; b.z *= inv; b.w *= inv;
    ((float4*)p)[tid] = a;
    ((float4*)p)[tid + 256] = b;
}

// ---------------------------------------------------------------------------
// out[row] = LayerNorm(A[row] + R[row]) * g + b  (row length = 512)
// One block (128 thr, 4 per thread) per row.
// ---------------------------------------------------------------------------
__global__ __launch_bounds__(128) void add_ln_k(
    const float* __restrict__ A, const float* __restrict__ R,
    const float* __restrict__ g, const float* __restrict__ be,
    float* __restrict__ O)
{
    const long row = blockIdx.x;
    const int tid = threadIdx.x;
    float4 vv = ((const float4*)(A + row * EMB))[tid];
    float4 rr = ((const float4*)(R + row * EMB))[tid];
    vv.x += rr.x; vv.y += rr.y; vv.z += rr.z; vv.w += rr.w;

    float s  = vv.x + vv.y + vv.z + vv.w;
    float ss = vv.x * vv.x + vv.y * vv.y + vv.z * vv.z + vv.w * vv.w;
#pragma unroll
    for (int o = 16; o; o >>= 1) {
        s  += __shfl_xor_sync(0xffffffffu, s,  o);
        ss += __shfl_xor_sync(0xffffffffu, ss, o);
    }
    __shared__ float sb[4], sb2[4];
    if ((tid & 31) == 0) { sb[tid >> 5] = s; sb2[tid >> 5] = ss; }
    __syncthreads();
    s  = sb[0]  + sb[1]  + sb[2]  + sb[3];
    ss = sb2[0] + sb2[1] + sb2[2] + sb2[3];

    const float mu   = s * (1.0f / EMB);
    const float var  = ss * (1.0f / EMB) - mu * mu;
    const float rstd = rsqrtf(var + 1e-5f);

    float4 gg = ((const float4*)g)[tid];
    float4 bb = ((const float4*)be)[tid];
    float4 o;
    o.x = (vv.x - mu) * rstd * gg.x + bb.x;
    o.y = (vv.y - mu) * rstd * gg.y + bb.y;
    o.z = (vv.z - mu) * rstd * gg.z + bb.z;
    o.w = (vv.w - mu) * rstd * gg.w + bb.w;
    ((float4*)(O + row * EMB))[tid] = o;
}

// ---------------------------------------------------------------------------
extern "C" void kernel_launch(void* const* d_in, const int* in_sizes, int n_in,
                              void* d_out, int out_size)
{
    const float* q     = (const float*)d_in[0];
    const float* k     = (const float*)d_in[1];
    const float* v     = (const float*)d_in[2];
    const float* ln1_g = (const float*)d_in[3];
    const float* ln1_b = (const float*)d_in[4];
    const float* w1    = (const float*)d_in[5];
    const float* b1    = (const float*)d_in[6];
    const float* w2    = (const float*)d_in[7];
    const float* b2    = (const float*)d_in[8];
    const float* ln3_g = (const float*)d_in[9];
    const float* ln3_b = (const float*)d_in[10];
    float* out = (float*)d_out;

    float *scores, *attn, *x, *h, *ff;
    cudaGetSymbolAddress((void**)&scores, g_scores);
    cudaGetSymbolAddress((void**)&attn,   g_attn);
    cudaGetSymbolAddress((void**)&x,      g_x);
    cudaGetSymbolAddress((void**)&h,      g_h);
    cudaGetSymbolAddress((void**)&ff,     g_ff);

    const float scale = 0.04419417382415922f;  // 1/sqrt(512)
    const long sQK = (long)SEQ * EMB;
    const long sSS = (long)SEQ * SEQ;
    const long sH  = (long)SEQ * HID;

    // 1) scores = scale * Q @ K^T     [per batch: 2048x2048x512, NT]
    gemm_k<true, 0><<<dim3(SEQ / GBN, SEQ / GBM, BATCH), 256>>>(
        q, k, nullptr, scores, SEQ, SEQ, EMB, sQK, sQK, sSS, scale);

    // 2) softmax rows
    softmax_k<<<BATCH * SEQ, 256>>>(scores);

    // 3) attn = P @ V                 [2048x512x2048, NN]
    gemm_k<false, 0><<<dim3(EMB / GBN, SEQ / GBM, BATCH), 256>>>(
        scores, v, nullptr, attn, SEQ, EMB, SEQ, sSS, sQK, sQK, 1.0f);

    // 4) x = LN(q + attn)
    add_ln_k<<<BATCH * SEQ, 128>>>(q, attn, ln1_g, ln1_b, x);

    // 5) h = gelu(x @ w1 + b1)        [2048x1024x512, NN, shared weights]
    gemm_k<false, 1><<<dim3(HID / GBN, SEQ / GBM, BATCH), 256>>>(
        x, w1, b1, h, SEQ, HID, EMB, sQK, 0L, sH, 1.0f);

    // 6) ff = h @ w2 + b2             [2048x512x1024, NN, shared weights]
    gemm_k<false, 2><<<dim3(EMB / GBN, SEQ / GBM, BATCH), 256>>>(
        h, w2, b2, ff, SEQ, EMB, HID, sH, 0L, sQK, 1.0f);

    // 7) out = LN(x + ff)
    add_ln_k<<<BATCH * SEQ, 128>>>(x, ff, ln3_g, ln3_b, out);
}

// round 7
// speedup vs baseline: 4.0541x; 4.0541x over previous
#include <cuda_runtime.h>
#include <cstdint>
#include <math.h>

// Problem constants
#define BATCH 16
#define SEQ   2048
#define EMB   512
#define HID   1024

// Scratch (device globals: allocation-free per harness rules)
__device__ float g_scores[(long)BATCH * SEQ * SEQ];   // 256 MB
__device__ float g_attn  [(long)BATCH * SEQ * EMB];
__device__ float g_x     [(long)BATCH * SEQ * EMB];
__device__ float g_xr    [(long)BATCH * SEQ * EMB];
__device__ float g_h     [(long)BATCH * SEQ * HID];
__device__ float g_ff    [(long)BATCH * SEQ * EMB];
__device__ float g_qr    [(long)BATCH * SEQ * EMB];
__device__ float g_kr    [(long)BATCH * SEQ * EMB];
__device__ float g_vt    [(long)BATCH * SEQ * EMB];
__device__ float g_w1t   [HID * EMB];
__device__ float g_w2t   [EMB * HID];

// ---------------------------------------------------------------------------
// PTX helpers (sm_80-baseline ISA only: mma.sync / ldmatrix / cp.async)
// ---------------------------------------------------------------------------
__device__ __forceinline__ uint32_t smem_u32(const void* p) {
    uint32_t a;
    asm("{ .reg .u64 t; cvta.to.shared.u64 t, %1; cvt.u32.u64 %0, t; }" : "=r"(a) : "l"(p));
    return a;
}
__device__ __forceinline__ float rna_tf32(float x) {
    float y; asm("cvt.rna.tf32.f32 %0, %1;" : "=f"(y) : "f"(x)); return y;
}
__device__ __forceinline__ void cp16(uint32_t dst, const void* src) {
    asm volatile("cp.async.cg.shared.global [%0], [%1], 16;" :: "r"(dst), "l"(src));
}
__device__ __forceinline__ void cp_commit() { asm volatile("cp.async.commit_group;" ::: "memory"); }
template <int N> __device__ __forceinline__ void cp_wait() {
    asm volatile("cp.async.wait_group %0;" :: "n"(N) : "memory");
}
#define SW128(x) ((x) ^ (((x) >> 3) & 0x70))

__device__ __forceinline__ void ldsm4(uint32_t* r, uint32_t addr) {
    asm volatile("ldmatrix.sync.aligned.m8n8.x4.shared.b16 {%0,%1,%2,%3}, [%4];"
        : "=r"(r[0]), "=r"(r[1]), "=r"(r[2]), "=r"(r[3]) : "r"(addr));
}
__device__ __forceinline__ void mma_tf32(float* c, const uint32_t* a, const uint32_t* b) {
    asm volatile(
        "mma.sync.aligned.m16n8k8.row.col.f32.tf32.tf32.f32 "
        "{%0,%1,%2,%3}, {%4,%5,%6,%7}, {%8,%9}, {%0,%1,%2,%3};"
        : "+f"(c[0]), "+f"(c[1]), "+f"(c[2]), "+f"(c[3])
        : "r"(a[0]), "r"(a[1]), "r"(a[2]), "r"(a[3]), "r"(b[0]), "r"(b[1]));
}

__device__ __forceinline__ float gelu_exact(float x) {
    return 0.5f * x * (1.0f + erff(x * 0.70710678118654752f));
}

// ---------------------------------------------------------------------------
// Tensor-core tf32 GEMM: C[M,N] = epi(A[M,K] @ B[N,K]^T)
// Both operands K-major row-major (B pre-transposed). Tile 128x128x32,
// 256 threads (8 warps 4x2, warp tile 32x64), 3-stage cp.async, SW128 SMEM.
// k-step address advance is XOR (not add): swizzle puts row bits into byte
// bits [4:6], so adding 32*ks could carry into the row field. XOR is exact.
// EPI: 0 = *alpha  1 = none  2 = +bias,gelu,rna  3 = +bias
// ---------------------------------------------------------------------------
#define KC 32
#define STG_BYTES 32768              // 16KB A + 16KB B per stage
#define GEMM_SMEM (3 * STG_BYTES)    // 96 KB

template <int EPI>
__global__ __launch_bounds__(256) void gemm_tc(
    const float* __restrict__ A, const float* __restrict__ B,
    const float* __restrict__ bias, float* __restrict__ C,
    int M, int N, int K, long sA, long sB, long sC, float alpha)
{
    extern __shared__ char smem[];
    const uint32_t sbase = smem_u32(smem);
    const int tid = threadIdx.x, wid = tid >> 5, lane = tid & 31;
    const int warp_m = wid & 3, warp_n = wid >> 2;
    const int bz = blockIdx.z;
    A += (long)bz * sA;  B += (long)bz * sB;  C += (long)bz * sC;
    const int bm = blockIdx.y * 128, bn = blockIdx.x * 128;

    const char* Ap = (const char*)(A + (long)bm * K);
    const char* Bp = (const char*)(B + (long)bn * K);
    const long rowK = (long)K * 4;
    const int nk = K / KC;

    // cp.async: each stage = 128 rows x 128B for A and B. 1024 chunks of 16B
    // per matrix; each thread loads 4 A chunks + 4 B chunks.
    int ld_row[4]; uint32_t ld_sw[4];
#pragma unroll
    for (int i = 0; i < 4; i++) {
        int c = tid + i * 256;
        ld_row[i] = c >> 3;
        ld_sw[i] = SW128((uint32_t)((c >> 3) * 128 + (c & 7) * 16));
    }
    auto load_stage = [&](int s, int kt) {
        const uint32_t sa = sbase + (uint32_t)s * STG_BYTES;
        const uint32_t sbB = sa + 16384u;
        const long kb = (long)kt * 128;
#pragma unroll
        for (int i = 0; i < 4; i++) {
            long gsrc = (long)ld_row[i] * rowK + kb + ((tid + i * 256) & 7) * 16;
            cp16(sa  + ld_sw[i], Ap + gsrc);
            cp16(sbB + ld_sw[i], Bp + gsrc);
        }
        cp_commit();
    };

    // Per-lane swizzled ldmatrix base offsets within a stage.
    uint32_t offA[2], offB[4];
#pragma unroll
    for (int mt = 0; mt < 2; mt++) {
        int row = warp_m * 32 + mt * 16 + (lane & 15);
        offA[mt] = SW128((uint32_t)(row * 128 + (lane >> 4) * 16));
    }
#pragma unroll
    for (int np = 0; np < 4; np++) {
        int row = warp_n * 64 + np * 16 + (lane & 7) + ((lane >> 4) & 1) * 8;
        offB[np] = SW128((uint32_t)(row * 128 + ((lane >> 3) & 1) * 16)) + 16384u;
    }

    float acc[2][8][4];
#pragma unroll
    for (int mt = 0; mt < 2; mt++)
#pragma unroll
        for (int nt = 0; nt < 8; nt++)
#pragma unroll
            for (int i = 0; i < 4; i++) acc[mt][nt][i] = 0.0f;

    // Prologue: fill 2 stages
    load_stage(0, 0);
    if (nk > 1) load_stage(1, 1);

    for (int kt = 0; kt < nk; kt++) {
        const int s = kt % 3;
        if (kt + 1 < nk) cp_wait<1>(); else cp_wait<0>();
        __syncthreads();
        if (kt + 2 < nk) load_stage((kt + 2) % 3, kt + 2);

        const uint32_t sg = sbase + (uint32_t)s * STG_BYTES;
#pragma unroll
        for (int ks = 0; ks < 4; ks++) {
            const uint32_t kx = (uint32_t)(ks * 32);
            uint32_t af[2][4], bf[4][4];
#pragma unroll
            for (int mt = 0; mt < 2; mt++) ldsm4(af[mt], sg + (offA[mt] ^ kx));
#pragma unroll
            for (int np = 0; np < 4; np++) ldsm4(bf[np], sg + (offB[np] ^ kx));
#pragma unroll
            for (int mt = 0; mt < 2; mt++)
#pragma unroll
                for (int np = 0; np < 4; np++) {
                    mma_tf32(acc[mt][np * 2 + 0], af[mt], &bf[np][0]);
                    mma_tf32(acc[mt][np * 2 + 1], af[mt], &bf[np][2]);
                }
        }
        __syncthreads();
    }

    // Epilogue: c0,c1 = (row g, cols 2t,2t+1); c2,c3 = row g+8.
    const int g = lane >> 2, t = lane & 3;
#pragma unroll
    for (int mt = 0; mt < 2; mt++) {
#pragma unroll
        for (int half = 0; half < 2; half++) {
            long row = bm + warp_m * 32 + mt * 16 + g + half * 8;
            float* Crow = C + row * (long)N + bn + warp_n * 64 + t * 2;
#pragma unroll
            for (int nt = 0; nt < 8; nt++) {
                float2 v;
                v.x = acc[mt][nt][half * 2 + 0];
                v.y = acc[mt][nt][half * 2 + 1];
                if (EPI == 0) {
                    v.x *= alpha; v.y *= alpha;
                } else if (EPI >= 2) {
                    int col = bn + warp_n * 64 + nt * 8 + t * 2;
                    v.x += bias[col]; v.y += bias[col + 1];
                    if (EPI == 2) {
                        v.x = rna_tf32(gelu_exact(v.x));
                        v.y = rna_tf32(gelu_exact(v.y));
                    }
                }
                *(float2*)&Crow[nt * 8] = v;
            }
        }
    }
}

// ---------------------------------------------------------------------------
// Elementwise RNA round copy (for q, k)
// ---------------------------------------------------------------------------
__global__ __launch_bounds__(256) void round4_k(const float* __restrict__ in, float* __restrict__ out)
{
    long i = (long)blockIdx.x * blockDim.x + threadIdx.x;
    float4 v = ((const float4*)in)[i];
    v.x = rna_tf32(v.x); v.y = rna_tf32(v.y); v.z = rna_tf32(v.z); v.w = rna_tf32(v.w);
    ((float4*)out)[i] = v;
}

// ---------------------------------------------------------------------------
// Transpose + RNA round: in [R,C] -> out [C,R], batched
// ---------------------------------------------------------------------------
__global__ __launch_bounds__(256) void transpose_rna_k(
    const float* __restrict__ in, float* __restrict__ out,
    int R, int C, long sIn, long sOut)
{
    __shared__ float tb[32][33];
    in  += (long)blockIdx.z * sIn;
    out += (long)blockIdx.z * sOut;
    int c0 = blockIdx.x * 32, r0 = blockIdx.y * 32;
    int tx = threadIdx.x, ty = threadIdx.y;   // 32x8
#pragma unroll
    for (int i = 0; i < 32; i += 8)
        tb[ty + i][tx] = in[(long)(r0 + ty + i) * C + c0 + tx];
    __syncthreads();
#pragma unroll
    for (int i = 0; i < 32; i += 8)
        out[(long)(c0 + ty + i) * R + r0 + tx] = rna_tf32(tb[tx][ty + i]);
}

// ---------------------------------------------------------------------------
// Row softmax over 2048 columns, in place, RNA-rounded output (P is GEMM input)
// ---------------------------------------------------------------------------
__global__ __launch_bounds__(256) void softmax_k(float* __restrict__ sc)
{
    float* p = sc + (long)blockIdx.x * SEQ;
    const int tid = threadIdx.x;
    float4 a = ((const float4*)p)[tid];
    float4 b = ((const float4*)p)[tid + 256];

    float mx = fmaxf(fmaxf(fmaxf(a.x, a.y), fmaxf(a.z, a.w)),
                     fmaxf(fmaxf(b.x, b.y), fmaxf(b.z, b.w)));
#pragma unroll
    for (int o = 16; o; o >>= 1) mx = fmaxf(mx, __shfl_xor_sync(0xffffffffu, mx, o));
    __shared__ float red[8];
    if ((tid & 31) == 0) red[tid >> 5] = mx;
    __syncthreads();
    mx = red[0];
#pragma unroll
    for (int i = 1; i < 8; i++) mx = fmaxf(mx, red[i]);
    __syncthreads();

    a.x = expf(a.x - mx); a.y = expf(a.y - mx); a.z = expf(a.z - mx); a.w = expf(a.w - mx);
    b.x = expf(b.x - mx); b.y = expf(b.y - mx); b.z = expf(b.z - mx); b.w = expf(b.w - mx);
    float s = a.x + a.y + a.z + a.w + b.x + b.y + b.z + b.w;
#pragma unroll
    for (int o = 16; o; o >>= 1) s += __shfl_xor_sync(0xffffffffu, s, o);
    if ((tid & 31) == 0) red[tid >> 5] = s;
    __syncthreads();
    s = red[0] + red[1] + red[2] + red[3] + red[4] + red[5] + red[6] + red[7];

    float inv = 1.0f / s;
    a.x = rna_tf32(a.x * inv); a.y = rna_tf32(a.y * inv);
    a.z = rna_tf32(a.z * inv); a.w = rna_tf32(a.w * inv);
    b.x = rna_tf32(b.x * inv); b.y = rna_tf32(b.y * inv);
    b.z = rna_tf32(b.z * inv); b.w = rna_tf32(b.w * inv);
    ((float4*)p)[tid] = a;
    ((float4*)p)[tid + 256] = b;
}

// ---------------------------------------------------------------------------
// out = LayerNorm(A + R) * g + b ; optional RNA-rounded copy Or (GEMM input)
// ---------------------------------------------------------------------------
__global__ __launch_bounds__(128) void add_ln_k(
    const float* __restrict__ A, const float* __restrict__ R,
    const float* __restrict__ g, const float* __restrict__ be,
    float* __restrict__ O, float* __restrict__ Or)
{
    const long row = blockIdx.x;
    const int tid = threadIdx.x;
    float4 vv = ((const float4*)(A + row * EMB))[tid];
    float4 rr = ((const float4*)(R + row * EMB))[tid];
    vv.x += rr.x; vv.y += rr.y; vv.z += rr.z; vv.w += rr.w;

    float s  = vv.x + vv.y + vv.z + vv.w;
    float ss = vv.x * vv.x + vv.y * vv.y + vv.z * vv.z + vv.w * vv.w;
#pragma unroll
    for (int o = 16; o; o >>= 1) {
        s  += __shfl_xor_sync(0xffffffffu, s,  o);
        ss += __shfl_xor_sync(0xffffffffu, ss, o);
    }
    __shared__ float sb1[4], sb2[4];
    if ((tid & 31) == 0) { sb1[tid >> 5] = s; sb2[tid >> 5] = ss; }
    __syncthreads();
    s  = sb1[0] + sb1[1] + sb1[2] + sb1[3];
    ss = sb2[0] + sb2[1] + sb2[2] + sb2[3];

    const float mu   = s * (1.0f / EMB);
    const float var  = ss * (1.0f / EMB) - mu * mu;
    const float rstd = rsqrtf(var + 1e-5f);

    float4 gg = ((const float4*)g)[tid];
    float4 bb = ((const float4*)be)[tid];
    float4 o;
    o.x = (vv.x - mu) * rstd * gg.x + bb.x;
    o.y = (vv.y - mu) * rstd * gg.y + bb.y;
    o.z = (vv.z - mu) * rstd * gg.z + bb.z;
    o.w = (vv.w - mu) * rstd * gg.w + bb.w;
    ((float4*)(O + row * EMB))[tid] = o;
    if (Or) {
        float4 q;
        q.x = rna_tf32(o.x); q.y = rna_tf32(o.y);
        q.z = rna_tf32(o.z); q.w = rna_tf32(o.w);
        ((float4*)(Or + row * EMB))[tid] = q;
    }
}

// ---------------------------------------------------------------------------
extern "C" void kernel_launch(void* const* d_in, const int* in_sizes, int n_in,
                              void* d_out, int out_size)
{
    const float* q     = (const float*)d_in[0];
    const float* k     = (const float*)d_in[1];
    const float* v     = (const float*)d_in[2];
    const float* ln1_g = (const float*)d_in[3];
    const float* ln1_b = (const float*)d_in[4];
    const float* w1    = (const float*)d_in[5];
    const float* b1    = (const float*)d_in[6];
    const float* w2    = (const float*)d_in[7];
    const float* b2    = (const float*)d_in[8];
    const float* ln3_g = (const float*)d_in[9];
    const float* ln3_b = (const float*)d_in[10];
    float* out = (float*)d_out;

    float *scores, *attn, *x, *xr, *h, *ff, *qr, *kr, *vt, *w1t, *w2t;
    cudaGetSymbolAddress((void**)&scores, g_scores);
    cudaGetSymbolAddress((void**)&attn,   g_attn);
    cudaGetSymbolAddress((void**)&x,      g_x);
    cudaGetSymbolAddress((void**)&xr,     g_xr);
    cudaGetSymbolAddress((void**)&h,      g_h);
    cudaGetSymbolAddress((void**)&ff,     g_ff);
    cudaGetSymbolAddress((void**)&qr,     g_qr);
    cudaGetSymbolAddress((void**)&kr,     g_kr);
    cudaGetSymbolAddress((void**)&vt,     g_vt);
    cudaGetSymbolAddress((void**)&w1t,    g_w1t);
    cudaGetSymbolAddress((void**)&w2t,    g_w2t);

    cudaFuncSetAttribute(gemm_tc<0>, cudaFuncAttributeMaxDynamicSharedMemorySize, GEMM_SMEM);
    cudaFuncSetAttribute(gemm_tc<1>, cudaFuncAttributeMaxDynamicSharedMemorySize, GEMM_SMEM);
    cudaFuncSetAttribute(gemm_tc<2>, cudaFuncAttributeMaxDynamicSharedMemorySize, GEMM_SMEM);
    cudaFuncSetAttribute(gemm_tc<3>, cudaFuncAttributeMaxDynamicSharedMemorySize, GEMM_SMEM);

    const float scale = 0.04419417382415922f;  // 1/sqrt(512)
    const long sQK = (long)SEQ * EMB;
    const long sSS = (long)SEQ * SEQ;
    const long sH  = (long)SEQ * HID;

    // 0) tf32-RNA preprocessing of GEMM inputs
    round4_k<<<(BATCH * SEQ * EMB) / (256 * 4), 256>>>(q, qr);
    round4_k<<<(BATCH * SEQ * EMB) / (256 * 4), 256>>>(k, kr);
    transpose_rna_k<<<dim3(EMB / 32, SEQ / 32, BATCH), dim3(32, 8)>>>(v, vt, SEQ, EMB, sQK, sQK);
    transpose_rna_k<<<dim3(HID / 32, EMB / 32, 1), dim3(32, 8)>>>(w1, w1t, EMB, HID, 0L, 0L);
    transpose_rna_k<<<dim3(EMB / 32, HID / 32, 1), dim3(32, 8)>>>(w2, w2t, HID, EMB, 0L, 0L);

    // 1) scores = scale * qr @ kr^T
    gemm_tc<0><<<dim3(SEQ / 128, SEQ / 128, BATCH), 256, GEMM_SMEM>>>(
        qr, kr, nullptr, scores, SEQ, SEQ, EMB, sQK, sQK, sSS, scale);

    // 2) softmax rows (rounds P)
    softmax_k<<<BATCH * SEQ, 256>>>(scores);

    // 3) attn = P @ vt^T
    gemm_tc<1><<<dim3(EMB / 128, SEQ / 128, BATCH), 256, GEMM_SMEM>>>(
        scores, vt, nullptr, attn, SEQ, EMB, SEQ, sSS, sQK, sQK, 1.0f);

    // 4) x = LN(q + attn)  (exact x + rounded copy xr)
    add_ln_k<<<BATCH * SEQ, 128>>>(q, attn, ln1_g, ln1_b, x, xr);

    // 5) h = rna(gelu(xr @ w1t^T + b1))
    gemm_tc<2><<<dim3(HID / 128, SEQ / 128, BATCH), 256, GEMM_SMEM>>>(
        xr, w1t, b1, h, SEQ, HID, EMB, sQK, 0L, sH, 1.0f);

    // 6) ff = h @ w2t^T + b2
    gemm_tc<3><<<dim3(EMB / 128, SEQ / 128, BATCH), 256, GEMM_SMEM>>>(
        h, w2t, b2, ff, SEQ, EMB, HID, sH, 0L, sQK, 1.0f);

    // 7) out = LN(x + ff)
    add_ln_k<<<BATCH * SEQ, 128>>>(x, ff, ln3_g, ln3_b, out, nullptr);
}

// round 8
// speedup vs baseline: 6.0259x; 1.4864x over previous
#include <cuda_runtime.h>
#include <cuda_fp16.h>
#include <cstdint>
#include <math.h>

// Problem constants
#define BATCH 16
#define SEQ   2048
#define EMB   512
#define HID   1024

// Scratch (device globals: allocation-free per harness rules)
__device__ float  g_scores[(long)BATCH * SEQ * SEQ];   // 256 MB fp32 scores
__device__ __half g_p     [(long)BATCH * SEQ * SEQ];   // 128 MB half P
__device__ float  g_attn  [(long)BATCH * SEQ * EMB];
__device__ float  g_x     [(long)BATCH * SEQ * EMB];
__device__ __half g_xh    [(long)BATCH * SEQ * EMB];
__device__ __half g_h     [(long)BATCH * SEQ * HID];
__device__ float  g_ff    [(long)BATCH * SEQ * EMB];
__device__ __half g_qh    [(long)BATCH * SEQ * EMB];
__device__ __half g_kh    [(long)BATCH * SEQ * EMB];
__device__ __half g_vth   [(long)BATCH * SEQ * EMB];   // V^T per batch [E,S]
__device__ __half g_w1th  [HID * EMB];                 // w1^T [H,E]
__device__ __half g_w2th  [EMB * HID];                 // w2^T [E,H]

// ---------------------------------------------------------------------------
// PTX helpers (sm_80-baseline ISA: mma.sync / ldmatrix / cp.async)
// ---------------------------------------------------------------------------
__device__ __forceinline__ uint32_t smem_u32(const void* p) {
    uint32_t a;
    asm("{ .reg .u64 t; cvta.to.shared.u64 t, %1; cvt.u32.u64 %0, t; }" : "=r"(a) : "l"(p));
    return a;
}
__device__ __forceinline__ void cp16(uint32_t dst, const void* src) {
    asm volatile("cp.async.cg.shared.global [%0], [%1], 16;" :: "r"(dst), "l"(src));
}
__device__ __forceinline__ void cp_commit() { asm volatile("cp.async.commit_group;" ::: "memory"); }
template <int N> __device__ __forceinline__ void cp_wait() {
    asm volatile("cp.async.wait_group %0;" :: "n"(N) : "memory");
}
#define SW128(x) ((x) ^ (((x) >> 3) & 0x70))

__device__ __forceinline__ void ldsm4(uint32_t* r, uint32_t addr) {
    asm volatile("ldmatrix.sync.aligned.m8n8.x4.shared.b16 {%0,%1,%2,%3}, [%4];"
        : "=r"(r[0]), "=r"(r[1]), "=r"(r[2]), "=r"(r[3]) : "r"(addr));
}
__device__ __forceinline__ void mma_f16(float* c, const uint32_t* a, uint32_t b0, uint32_t b1) {
    asm volatile(
        "mma.sync.aligned.m16n8k16.row.col.f32.f16.f16.f32 "
        "{%0,%1,%2,%3}, {%4,%5,%6,%7}, {%8,%9}, {%0,%1,%2,%3};"
        : "+f"(c[0]), "+f"(c[1]), "+f"(c[2]), "+f"(c[3])
        : "r"(a[0]), "r"(a[1]), "r"(a[2]), "r"(a[3]), "r"(b0), "r"(b1));
}

__device__ __forceinline__ float gelu_exact(float x) {
    return 0.5f * x * (1.0f + erff(x * 0.70710678118654752f));
}

// ---------------------------------------------------------------------------
// fp16 tensor-core GEMM: C[M,N] = epi(A[M,K] @ B[N,K]^T), fp32 accumulate.
// A,B half K-major. Tile 128x128, KC=64 halves/stage (128B rows, SW128),
// 256 threads (8 warps 4x2, warp tile 32x64), 3-stage cp.async.
// k16-step address advance is XOR (swizzle-safe, bits 5-6 only).
// EPI: 0 = *alpha (float out)  1 = none (float out)
//      2 = +bias, gelu (half out)  3 = +bias (float out)
// ---------------------------------------------------------------------------
#define KC 64
#define STG_BYTES 32768              // 16KB A + 16KB B per stage
#define GEMM_SMEM (3 * STG_BYTES)    // 96 KB

template <int EPI, typename OutT>
__global__ __launch_bounds__(256) void gemm_h(
    const __half* __restrict__ A, const __half* __restrict__ B,
    const float* __restrict__ bias, OutT* __restrict__ C,
    int M, int N, int K, long sA, long sB, long sC, float alpha)
{
    extern __shared__ char smem[];
    const uint32_t sbase = smem_u32(smem);
    const int tid = threadIdx.x, wid = tid >> 5, lane = tid & 31;
    const int warp_m = wid & 3, warp_n = wid >> 2;
    const int bz = blockIdx.z;
    A += (long)bz * sA;  B += (long)bz * sB;  C += (long)bz * sC;
    const int bm = blockIdx.y * 128, bn = blockIdx.x * 128;

    const char* Ap = (const char*)(A + (long)bm * K);
    const char* Bp = (const char*)(B + (long)bn * K);
    const long rowK = (long)K * 2;
    const int nk = K / KC;

    // cp.async: each stage = 128 rows x 128B per matrix = 1024 chunks of 16B;
    // each thread loads 4 A chunks + 4 B chunks.
    int ld_row[4]; uint32_t ld_sw[4];
#pragma unroll
    for (int i = 0; i < 4; i++) {
        int c = tid + i * 256;
        ld_row[i] = c >> 3;
        ld_sw[i] = SW128((uint32_t)((c >> 3) * 128 + (c & 7) * 16));
    }
    auto load_stage = [&](int s, int kt) {
        const uint32_t sa = sbase + (uint32_t)s * STG_BYTES;
        const uint32_t sbB = sa + 16384u;
        const long kb = (long)kt * 128;
#pragma unroll
        for (int i = 0; i < 4; i++) {
            long gsrc = (long)ld_row[i] * rowK + kb + ((tid + i * 256) & 7) * 16;
            cp16(sa  + ld_sw[i], Ap + gsrc);
            cp16(sbB + ld_sw[i], Bp + gsrc);
        }
        cp_commit();
    };

    // ldmatrix base offsets. For fp16, A (16x16) and B (16n x 16k) use the
    // same pattern: row = tilebase + (lane&15), byte = (lane>>4)*16.
    uint32_t offA[2], offB[4];
#pragma unroll
    for (int mt = 0; mt < 2; mt++) {
        int row = warp_m * 32 + mt * 16 + (lane & 15);
        offA[mt] = SW128((uint32_t)(row * 128 + (lane >> 4) * 16));
    }
#pragma unroll
    for (int np = 0; np < 4; np++) {
        int row = warp_n * 64 + np * 16 + (lane & 15);
        offB[np] = SW128((uint32_t)(row * 128 + (lane >> 4) * 16)) + 16384u;
    }

    float acc[2][8][4];
#pragma unroll
    for (int mt = 0; mt < 2; mt++)
#pragma unroll
        for (int nt = 0; nt < 8; nt++)
#pragma unroll
            for (int i = 0; i < 4; i++) acc[mt][nt][i] = 0.0f;

    load_stage(0, 0);
    if (nk > 1) load_stage(1, 1);

    for (int kt = 0; kt < nk; kt++) {
        const int s = kt % 3;
        if (kt + 1 < nk) cp_wait<1>(); else cp_wait<0>();
        __syncthreads();
        if (kt + 2 < nk) load_stage((kt + 2) % 3, kt + 2);

        const uint32_t sg = sbase + (uint32_t)s * STG_BYTES;
#pragma unroll
        for (int ks = 0; ks < 4; ks++) {       // 4 x k16 = KC
            const uint32_t kx = (uint32_t)(ks * 32);
            uint32_t af[2][4], bf[4][4];
#pragma unroll
            for (int mt = 0; mt < 2; mt++) ldsm4(af[mt], sg + (offA[mt] ^ kx));
#pragma unroll
            for (int np = 0; np < 4; np++) ldsm4(bf[np], sg + (offB[np] ^ kx));
            // bf[np]: r0=(n0-7,k0-7) r1=(n8-15,k0-7) r2=(n0-7,k8-15) r3=(n8-15,k8-15)
#pragma unroll
            for (int mt = 0; mt < 2; mt++)
#pragma unroll
                for (int np = 0; np < 4; np++) {
                    mma_f16(acc[mt][np * 2 + 0], af[mt], bf[np][0], bf[np][2]);
                    mma_f16(acc[mt][np * 2 + 1], af[mt], bf[np][1], bf[np][3]);
                }
        }
        __syncthreads();
    }

    // Epilogue: c0,c1 = (row g, cols 2t,2t+1); c2,c3 = row g+8.
    const int g = lane >> 2, t = lane & 3;
#pragma unroll
    for (int mt = 0; mt < 2; mt++) {
#pragma unroll
        for (int half_ = 0; half_ < 2; half_++) {
            long row = bm + warp_m * 32 + mt * 16 + g + half_ * 8;
            OutT* Crow = C + row * (long)N + bn + warp_n * 64 + t * 2;
#pragma unroll
            for (int nt = 0; nt < 8; nt++) {
                float vx = acc[mt][nt][half_ * 2 + 0];
                float vy = acc[mt][nt][half_ * 2 + 1];
                if (EPI == 0) {
                    vx *= alpha; vy *= alpha;
                } else if (EPI >= 2) {
                    int col = bn + warp_n * 64 + nt * 8 + t * 2;
                    vx += bias[col]; vy += bias[col + 1];
                    if (EPI == 2) { vx = gelu_exact(vx); vy = gelu_exact(vy); }
                }
                if (sizeof(OutT) == 2) {
                    *(__half2*)((__half*)Crow + nt * 8) = __floats2half2_rn(vx, vy);
                } else {
                    float2 v; v.x = vx; v.y = vy;
                    *(float2*)((float*)Crow + nt * 8) = v;
                }
            }
        }
    }
}

// ---------------------------------------------------------------------------
// Elementwise fp32 -> fp16 copy (q, k)
// ---------------------------------------------------------------------------
__global__ __launch_bounds__(256) void to_half_k(const float* __restrict__ in, __half* __restrict__ out)
{
    long i = (long)blockIdx.x * blockDim.x + threadIdx.x;
    float4 v = ((const float4*)in)[i];
    __half2* o = (__half2*)out + i * 2;
    o[0] = __floats2half2_rn(v.x, v.y);
    o[1] = __floats2half2_rn(v.z, v.w);
}

// ---------------------------------------------------------------------------
// Transpose fp32 [R,C] -> fp16 [C,R], batched
// ---------------------------------------------------------------------------
__global__ __launch_bounds__(256) void transpose_half_k(
    const float* __restrict__ in, __half* __restrict__ out,
    int R, int C, long sIn, long sOut)
{
    __shared__ float tb[32][33];
    in  += (long)blockIdx.z * sIn;
    out += (long)blockIdx.z * sOut;
    int c0 = blockIdx.x * 32, r0 = blockIdx.y * 32;
    int tx = threadIdx.x, ty = threadIdx.y;   // 32x8
#pragma unroll
    for (int i = 0; i < 32; i += 8)
        tb[ty + i][tx] = in[(long)(r0 + ty + i) * C + c0 + tx];
    __syncthreads();
#pragma unroll
    for (int i = 0; i < 32; i += 8)
        out[(long)(c0 + ty + i) * R + r0 + tx] = __float2half_rn(tb[tx][ty + i]);
}

// ---------------------------------------------------------------------------
// Row softmax: fp32 scores [row of 2048] -> fp16 P
// ---------------------------------------------------------------------------
__global__ __launch_bounds__(256) void softmax_k(
    const float* __restrict__ sc, __half* __restrict__ pout)
{
    const float* p = sc + (long)blockIdx.x * SEQ;
    __half2* po = (__half2*)(pout + (long)blockIdx.x * SEQ);
    const int tid = threadIdx.x;
    float4 a = ((const float4*)p)[tid];
    float4 b = ((const float4*)p)[tid + 256];

    float mx = fmaxf(fmaxf(fmaxf(a.x, a.y), fmaxf(a.z, a.w)),
                     fmaxf(fmaxf(b.x, b.y), fmaxf(b.z, b.w)));
#pragma unroll
    for (int o = 16; o; o >>= 1) mx = fmaxf(mx, __shfl_xor_sync(0xffffffffu, mx, o));
    __shared__ float red[8];
    if ((tid & 31) == 0) red[tid >> 5] = mx;
    __syncthreads();
    mx = red[0];
#pragma unroll
    for (int i = 1; i < 8; i++) mx = fmaxf(mx, red[i]);
    __syncthreads();

    a.x = expf(a.x - mx); a.y = expf(a.y - mx); a.z = expf(a.z - mx); a.w = expf(a.w - mx);
    b.x = expf(b.x - mx); b.y = expf(b.y - mx); b.z = expf(b.z - mx); b.w = expf(b.w - mx);
    float s = a.x + a.y + a.z + a.w + b.x + b.y + b.z + b.w;
#pragma unroll
    for (int o = 16; o; o >>= 1) s += __shfl_xor_sync(0xffffffffu, s, o);
    if ((tid & 31) == 0) red[tid >> 5] = s;
    __syncthreads();
    s = red[0] + red[1] + red[2] + red[3] + red[4] + red[5] + red[6] + red[7];

    float inv = 1.0f / s;
    po[tid * 2 + 0]   = __floats2half2_rn(a.x * inv, a.y * inv);
    po[tid * 2 + 1]   = __floats2half2_rn(a.z * inv, a.w * inv);
    po[(tid + 256) * 2 + 0] = __floats2half2_rn(b.x * inv, b.y * inv);
    po[(tid + 256) * 2 + 1] = __floats2half2_rn(b.z * inv, b.w * inv);
}

// ---------------------------------------------------------------------------
// out = LayerNorm(A + R) * g + b ; optional fp16 copy Oh (next GEMM input)
// ---------------------------------------------------------------------------
__global__ __launch_bounds__(128) void add_ln_k(
    const float* __restrict__ A, const float* __restrict__ R,
    const float* __restrict__ g, const float* __restrict__ be,
    float* __restrict__ O, __half* __restrict__ Oh)
{
    const long row = blockIdx.x;
    const int tid = threadIdx.x;
    float4 vv = ((const float4*)(A + row * EMB))[tid];
    float4 rr = ((const float4*)(R + row * EMB))[tid];
    vv.x += rr.x; vv.y += rr.y; vv.z += rr.z; vv.w += rr.w;

    float s  = vv.x + vv.y + vv.z + vv.w;
    float ss = vv.x * vv.x + vv.y * vv.y + vv.z * vv.z + vv.w * vv.w;
#pragma unroll
    for (int o = 16; o; o >>= 1) {
        s  += __shfl_xor_sync(0xffffffffu, s,  o);
        ss += __shfl_xor_sync(0xffffffffu, ss, o);
    }
    __shared__ float sb1[4], sb2[4];
    if ((tid & 31) == 0) { sb1[tid >> 5] = s; sb2[tid >> 5] = ss; }
    __syncthreads();
    s  = sb1[0] + sb1[1] + sb1[2] + sb1[3];
    ss = sb2[0] + sb2[1] + sb2[2] + sb2[3];

    const float mu   = s * (1.0f / EMB);
    const float var  = ss * (1.0f / EMB) - mu * mu;
    const float rstd = rsqrtf(var + 1e-5f);

    float4 gg = ((const float4*)g)[tid];
    float4 bb = ((const float4*)be)[tid];
    float4 o;
    o.x = (vv.x - mu) * rstd * gg.x + bb.x;
    o.y = (vv.y - mu) * rstd * gg.y + bb.y;
    o.z = (vv.z - mu) * rstd * gg.z + bb.z;
    o.w = (vv.w - mu) * rstd * gg.w + bb.w;
    ((float4*)(O + row * EMB))[tid] = o;
    if (Oh) {
        __half2* oh = (__half2*)(Oh + row * EMB) + tid * 2;
        oh[0] = __floats2half2_rn(o.x, o.y);
        oh[1] = __floats2half2_rn(o.z, o.w);
    }
}

// ---------------------------------------------------------------------------
extern "C" void kernel_launch(void* const* d_in, const int* in_sizes, int n_in,
                              void* d_out, int out_size)
{
    const float* q     = (const float*)d_in[0];
    const float* k     = (const float*)d_in[1];
    const float* v     = (const float*)d_in[2];
    const float* ln1_g = (const float*)d_in[3];
    const float* ln1_b = (const float*)d_in[4];
    const float* w1    = (const float*)d_in[5];
    const float* b1    = (const float*)d_in[6];
    const float* w2    = (const float*)d_in[7];
    const float* b2    = (const float*)d_in[8];
    const float* ln3_g = (const float*)d_in[9];
    const float* ln3_b = (const float*)d_in[10];
    float* out = (float*)d_out;

    float *scores, *attn, *x, *ff;
    __half *P, *xh, *h, *qh, *kh, *vth, *w1th, *w2th;
    cudaGetSymbolAddress((void**)&scores, g_scores);
    cudaGetSymbolAddress((void**)&P,      g_p);
    cudaGetSymbolAddress((void**)&attn,   g_attn);
    cudaGetSymbolAddress((void**)&x,      g_x);
    cudaGetSymbolAddress((void**)&xh,     g_xh);
    cudaGetSymbolAddress((void**)&h,      g_h);
    cudaGetSymbolAddress((void**)&ff,     g_ff);
    cudaGetSymbolAddress((void**)&qh,     g_qh);
    cudaGetSymbolAddress((void**)&kh,     g_kh);
    cudaGetSymbolAddress((void**)&vth,    g_vth);
    cudaGetSymbolAddress((void**)&w1th,   g_w1th);
    cudaGetSymbolAddress((void**)&w2th,   g_w2th);

    cudaFuncSetAttribute(gemm_h<0, float>,  cudaFuncAttributeMaxDynamicSharedMemorySize, GEMM_SMEM);
    cudaFuncSetAttribute(gemm_h<1, float>,  cudaFuncAttributeMaxDynamicSharedMemorySize, GEMM_SMEM);
    cudaFuncSetAttribute(gemm_h<2, __half>, cudaFuncAttributeMaxDynamicSharedMemorySize, GEMM_SMEM);
    cudaFuncSetAttribute(gemm_h<3, float>,  cudaFuncAttributeMaxDynamicSharedMemorySize, GEMM_SMEM);

    const float scale = 0.04419417382415922f;  // 1/sqrt(512)
    const long sQK = (long)SEQ * EMB;
    const long sSS = (long)SEQ * SEQ;
    const long sH  = (long)SEQ * HID;

    // 0) fp16 preprocessing of GEMM inputs
    to_half_k<<<(BATCH * SEQ * EMB) / (256 * 4), 256>>>(q, qh);
    to_half_k<<<(BATCH * SEQ * EMB) / (256 * 4), 256>>>(k, kh);
    transpose_half_k<<<dim3(EMB / 32, SEQ / 32, BATCH), dim3(32, 8)>>>(v, vth, SEQ, EMB, sQK, sQK);
    transpose_half_k<<<dim3(HID / 32, EMB / 32, 1), dim3(32, 8)>>>(w1, w1th, EMB, HID, 0L, 0L);
    transpose_half_k<<<dim3(EMB / 32, HID / 32, 1), dim3(32, 8)>>>(w2, w2th, HID, EMB, 0L, 0L);

    // 1) scores = scale * qh @ kh^T  (fp32 out — raw scores need absolute precision)
    gemm_h<0, float><<<dim3(SEQ / 128, SEQ / 128, BATCH), 256, GEMM_SMEM>>>(
        qh, kh, nullptr, scores, SEQ, SEQ, EMB, sQK, sQK, sSS, scale);

    // 2) softmax rows: fp32 scores -> fp16 P
    softmax_k<<<BATCH * SEQ, 256>>>(scores, P);

    // 3) attn = P @ vth^T (fp32 out)
    gemm_h<1, float><<<dim3(EMB / 128, SEQ / 128, BATCH), 256, GEMM_SMEM>>>(
        P, vth, nullptr, attn, SEQ, EMB, SEQ, sSS, sQK, sQK, 1.0f);

    // 4) x = LN(q + attn)  (fp32 x + fp16 copy xh)
    add_ln_k<<<BATCH * SEQ, 128>>>(q, attn, ln1_g, ln1_b, x, xh);

    // 5) h = half(gelu(xh @ w1th^T + b1))
    gemm_h<2, __half><<<dim3(HID / 128, SEQ / 128, BATCH), 256, GEMM_SMEM>>>(
        xh, w1th, b1, h, SEQ, HID, EMB, sQK, 0L, sH, 1.0f);

    // 6) ff = h @ w2th^T + b2 (fp32 out)
    gemm_h<3, float><<<dim3(EMB / 128, SEQ / 128, BATCH), 256, GEMM_SMEM>>>(
        h, w2th, b2, ff, SEQ, EMB, HID, sH, 0L, sQK, 1.0f);

    // 7) out = LN(x + ff)
    add_ln_k<<<BATCH * SEQ, 128>>>(x, ff, ln3_g, ln3_b, out, nullptr);
}